// round 1
// baseline (speedup 1.0000x reference)
#include <cuda_runtime.h>
#include <math.h>

#define BATCH 32768
#define NL 2

// ---------------- scratch (device globals; no allocation) ----------------
__device__ float g_xa[(size_t)BATCH * 256];   // modality A residual state
__device__ float g_xb[(size_t)BATCH * 256];   // modality B residual state
__device__ float g_xn[(size_t)BATCH * 256];   // rmsnorm output
__device__ float g_h [(size_t)BATCH * 512];   // post-conv silu activations
__device__ float g_g [(size_t)BATCH * 512];   // gate (raw proj, silu applied in ssm)
__device__ float g_y [(size_t)BATCH * 512];   // gated ssm output

__device__ __forceinline__ float silu_f(float x) {
    return x / (1.0f + __expf(-x));
}
__device__ __forceinline__ float softplus_f(float x) {
    // log1p(exp(x)) stable
    return (x > 20.0f) ? x : log1pf(__expf(x));
}

// ---------------- tiled fp32 GEMM: C[M,N] = A[M,K] @ W[N,K]^T ----------------
// MODE 0: out0[m*N+n] = acc + e0[n]                       (bias)
// MODE 1: n<512: h = silu(acc*conv_w[n*4+3] + conv_b[n]) -> out0[m*512+n]
//         n>=512: gate raw -> out1[m*512+(n-512)]
// MODE 2: out0[m*N+n] = acc + e0[m*N+n]                   (residual add, in-place ok)
#define BM 128
#define BN 64
#define BK 16

template<int MODE>
__global__ __launch_bounds__(256)
void gemm_kernel(const float* __restrict__ A, const float* __restrict__ W,
                 float* __restrict__ out0, float* __restrict__ out1,
                 const float* __restrict__ e0, const float* __restrict__ e1,
                 int N, int K)
{
    __shared__ float As[BK][BM];
    __shared__ float Bs[BK][BN];

    const int tid = threadIdx.x;
    const int tx  = tid & 15;       // 16 threads over N (x4 cols)
    const int ty  = tid >> 4;       // 16 threads over M (x8 rows)
    const int bm  = blockIdx.y * BM;
    const int bn  = blockIdx.x * BN;

    float acc[8][4];
    #pragma unroll
    for (int i = 0; i < 8; i++)
        #pragma unroll
        for (int j = 0; j < 4; j++) acc[i][j] = 0.0f;

    const bool vec = ((K & 3) == 0);

    for (int k0 = 0; k0 < K; k0 += BK) {
        // load A tile (128 rows x 16 k): 2 float4 per thread
        #pragma unroll
        for (int i = 0; i < 2; i++) {
            int id  = tid * 2 + i;           // 0..511
            int row = id >> 2;               // 0..127
            int kq  = (id & 3) * 4;          // 0,4,8,12
            int k   = k0 + kq;
            float4 v = make_float4(0.f, 0.f, 0.f, 0.f);
            if (vec) {
                if (k + 4 <= K)
                    v = *(const float4*)(A + (size_t)(bm + row) * K + k);
            } else {
                float t0 = (k + 0 < K) ? A[(size_t)(bm + row) * K + k + 0] : 0.f;
                float t1 = (k + 1 < K) ? A[(size_t)(bm + row) * K + k + 1] : 0.f;
                float t2 = (k + 2 < K) ? A[(size_t)(bm + row) * K + k + 2] : 0.f;
                float t3 = (k + 3 < K) ? A[(size_t)(bm + row) * K + k + 3] : 0.f;
                v = make_float4(t0, t1, t2, t3);
            }
            As[kq + 0][row] = v.x; As[kq + 1][row] = v.y;
            As[kq + 2][row] = v.z; As[kq + 3][row] = v.w;
        }
        // load W tile (64 rows x 16 k): 1 float4 per thread
        {
            int row = tid >> 2;              // 0..63
            int kq  = (tid & 3) * 4;
            int k   = k0 + kq;
            float4 v = make_float4(0.f, 0.f, 0.f, 0.f);
            if (vec) {
                if (k + 4 <= K)
                    v = *(const float4*)(W + (size_t)(bn + row) * K + k);
            } else {
                float t0 = (k + 0 < K) ? W[(size_t)(bn + row) * K + k + 0] : 0.f;
                float t1 = (k + 1 < K) ? W[(size_t)(bn + row) * K + k + 1] : 0.f;
                float t2 = (k + 2 < K) ? W[(size_t)(bn + row) * K + k + 2] : 0.f;
                float t3 = (k + 3 < K) ? W[(size_t)(bn + row) * K + k + 3] : 0.f;
                v = make_float4(t0, t1, t2, t3);
            }
            Bs[kq + 0][row] = v.x; Bs[kq + 1][row] = v.y;
            Bs[kq + 2][row] = v.z; Bs[kq + 3][row] = v.w;
        }
        __syncthreads();

        #pragma unroll
        for (int kk = 0; kk < BK; kk++) {
            float4 a0 = *(const float4*)&As[kk][ty * 8];
            float4 a1 = *(const float4*)&As[kk][ty * 8 + 4];
            float4 b  = *(const float4*)&Bs[kk][tx * 4];
            float am[8] = {a0.x, a0.y, a0.z, a0.w, a1.x, a1.y, a1.z, a1.w};
            float bv[4] = {b.x, b.y, b.z, b.w};
            #pragma unroll
            for (int i = 0; i < 8; i++)
                #pragma unroll
                for (int j = 0; j < 4; j++)
                    acc[i][j] = fmaf(am[i], bv[j], acc[i][j]);
        }
        __syncthreads();
    }

    #pragma unroll
    for (int i = 0; i < 8; i++) {
        int m = bm + ty * 8 + i;
        #pragma unroll
        for (int j = 0; j < 4; j++) {
            int n = bn + tx * 4 + j;
            float v = acc[i][j];
            if (MODE == 0) {
                out0[(size_t)m * N + n] = v + e0[n];
            } else if (MODE == 1) {
                if (n < 512) {
                    float t = fmaf(v, e0[n * 4 + 3], e1[n]);   // conv last tap + bias
                    out0[(size_t)m * 512 + n] = silu_f(t);
                } else {
                    out1[(size_t)m * 512 + (n - 512)] = v;      // raw gate
                }
            } else {  // MODE 2
                out0[(size_t)m * N + n] = v + e0[(size_t)m * N + n];
            }
        }
    }
}

// ---------------- fused SSM: x_proj(48) + B.C + dt expansion + gate ----------------
// warp per row, 8 rows per block.
__global__ __launch_bounds__(256)
void ssm_kernel(const float* __restrict__ h, const float* __restrict__ gate,
                const float* __restrict__ xp_w,   // [48,512]
                const float* __restrict__ dt_w,   // [512,16]
                const float* __restrict__ dt_b,   // [512]
                const float* __restrict__ Dv,     // [512]
                float* __restrict__ y)
{
    const int warp = threadIdx.x >> 5;
    const int lane = threadIdx.x & 31;
    const size_t row = (size_t)blockIdx.x * 8 + warp;

    const float* hr = h + row * 512;
    float hreg[16];
    #pragma unroll
    for (int q = 0; q < 16; q++) hreg[q] = hr[lane + 32 * q];

    float dtv[16], bn[16];
    float bc = 0.0f;
    #pragma unroll
    for (int j = 0; j < 48; j++) {
        const float* w = xp_w + j * 512;
        float p = 0.0f;
        #pragma unroll
        for (int q = 0; q < 16; q++) p = fmaf(hreg[q], w[lane + 32 * q], p);
        #pragma unroll
        for (int o = 16; o > 0; o >>= 1) p += __shfl_xor_sync(0xffffffffu, p, o);
        if (j < 16)       dtv[j] = p;
        else if (j < 32)  bn[j - 16] = p;
        else              bc = fmaf(bn[j - 32], p, bc);
    }

    #pragma unroll
    for (int q = 0; q < 16; q++) {
        int i = lane + 32 * q;
        const float4* wr = (const float4*)(dt_w + (size_t)i * 16);
        float t = dt_b[i];
        #pragma unroll
        for (int c = 0; c < 4; c++) {
            float4 w4 = wr[c];
            t = fmaf(dtv[c * 4 + 0], w4.x, t);
            t = fmaf(dtv[c * 4 + 1], w4.y, t);
            t = fmaf(dtv[c * 4 + 2], w4.z, t);
            t = fmaf(dtv[c * 4 + 3], w4.w, t);
        }
        float sp = softplus_f(t);
        float gv = gate[row * 512 + i];
        y[row * 512 + i] = hreg[q] * fmaf(sp, bc, Dv[i]) * silu_f(gv);
    }
}

// ---------------- rmsnorm over 256, warp per row ----------------
__global__ __launch_bounds__(256)
void rmsnorm_kernel(const float* __restrict__ x, const float* __restrict__ w,
                    float* __restrict__ out)
{
    const int warp = threadIdx.x >> 5;
    const int lane = threadIdx.x & 31;
    const size_t row = (size_t)blockIdx.x * 8 + warp;

    float v[8];
    float ss = 0.0f;
    #pragma unroll
    for (int q = 0; q < 8; q++) {
        v[q] = x[row * 256 + lane + 32 * q];
        ss = fmaf(v[q], v[q], ss);
    }
    #pragma unroll
    for (int o = 16; o > 0; o >>= 1) ss += __shfl_xor_sync(0xffffffffu, ss, o);
    float inv = rsqrtf(ss * (1.0f / 256.0f) + 1e-5f);
    #pragma unroll
    for (int q = 0; q < 8; q++)
        out[row * 256 + lane + 32 * q] = v[q] * inv * w[lane + 32 * q];
}

// ---------------- classifier: pooled=(xa+xb)/2 ; logits = pooled @ cls_w^T + b ----------------
__global__ __launch_bounds__(256)
void cls_kernel(const float* __restrict__ xa, const float* __restrict__ xb,
                const float* __restrict__ cw, const float* __restrict__ cb,
                float* __restrict__ out)
{
    const int warp = threadIdx.x >> 5;
    const int lane = threadIdx.x & 31;
    const size_t row = (size_t)blockIdx.x * 8 + warp;

    float p[8];
    #pragma unroll
    for (int q = 0; q < 8; q++) {
        size_t idx = row * 256 + lane + 32 * q;
        p[q] = 0.5f * (xa[idx] + xb[idx]);
    }
    #pragma unroll
    for (int j = 0; j < 5; j++) {
        float s = 0.0f;
        #pragma unroll
        for (int q = 0; q < 8; q++) s = fmaf(p[q], cw[j * 256 + lane + 32 * q], s);
        #pragma unroll
        for (int o = 16; o > 0; o >>= 1) s += __shfl_xor_sync(0xffffffffu, s, o);
        if (lane == 0) out[row * 5 + j] = s + cb[j];
    }
}

// ---------------- launch ----------------
extern "C" void kernel_launch(void* const* d_in, const int* in_sizes, int n_in,
                              void* d_out, int out_size)
{
    const float* methyl   = (const float*)d_in[0];   // [B,500]
    const float* rna      = (const float*)d_in[1];   // [B,47]
    const float* methyl_w = (const float*)d_in[2];   // [256,500]
    const float* methyl_b = (const float*)d_in[3];   // [256]
    const float* rna_w    = (const float*)d_in[4];   // [256,47]
    const float* rna_b    = (const float*)d_in[5];   // [256]
    const float* in_w     = (const float*)d_in[6];   // [2,1024,256]
    const float* conv_w   = (const float*)d_in[7];   // [2,512,4]
    const float* conv_b   = (const float*)d_in[8];   // [2,512]
    const float* xp_w     = (const float*)d_in[9];   // [2,48,512]
    const float* dt_w     = (const float*)d_in[10];  // [2,512,16]
    const float* dt_b     = (const float*)d_in[11];  // [2,512]
    // d_in[12] = A_log : provably unused (scan starts from zero state, L=1)
    const float* Dv       = (const float*)d_in[13];  // [2,512]
    const float* out_w    = (const float*)d_in[14];  // [2,256,512]
    const float* norm_w   = (const float*)d_in[15];  // [2,256]
    const float* norm_f_w = (const float*)d_in[16];  // [256]
    const float* cls_w    = (const float*)d_in[17];  // [5,256]
    const float* cls_b    = (const float*)d_in[18];  // [5]
    float* out = (float*)d_out;

    float* g_xa_p; cudaGetSymbolAddress((void**)&g_xa_p, g_xa);
    float* g_xb_p; cudaGetSymbolAddress((void**)&g_xb_p, g_xb);
    float* g_xn_p; cudaGetSymbolAddress((void**)&g_xn_p, g_xn);
    float* g_h_p;  cudaGetSymbolAddress((void**)&g_h_p,  g_h);
    float* g_g_p;  cudaGetSymbolAddress((void**)&g_g_p,  g_g);
    float* g_y_p;  cudaGetSymbolAddress((void**)&g_y_p,  g_y);

    const int M = BATCH;
    dim3 blk(256);
    dim3 grid_emb(256 / BN, M / BM);       // N=256
    dim3 grid_proj(1024 / BN, M / BM);     // N=1024
    dim3 grid_out(256 / BN, M / BM);       // N=256
    dim3 grid_row(M / 8);

    // embeddings
    gemm_kernel<0><<<grid_emb, blk>>>(methyl, methyl_w, g_xa_p, nullptr, methyl_b, nullptr, 256, 500);
    gemm_kernel<0><<<grid_emb, blk>>>(rna,    rna_w,    g_xb_p, nullptr, rna_b,    nullptr, 256, 47);

    float* states[2] = { g_xa_p, g_xb_p };
    for (int s = 0; s < 2; s++) {
        float* x = states[s];
        for (int l = 0; l < NL; l++) {
            rmsnorm_kernel<<<grid_row, blk>>>(x, norm_w + l * 256, g_xn_p);
            gemm_kernel<1><<<grid_proj, blk>>>(g_xn_p, in_w + (size_t)l * 1024 * 256,
                                               g_h_p, g_g_p,
                                               conv_w + (size_t)l * 512 * 4,
                                               conv_b + (size_t)l * 512, 1024, 256);
            ssm_kernel<<<grid_row, blk>>>(g_h_p, g_g_p,
                                          xp_w + (size_t)l * 48 * 512,
                                          dt_w + (size_t)l * 512 * 16,
                                          dt_b + (size_t)l * 512,
                                          Dv   + (size_t)l * 512, g_y_p);
            gemm_kernel<2><<<grid_out, blk>>>(g_y_p, out_w + (size_t)l * 256 * 512,
                                              x, nullptr, x, nullptr, 256, 512);
        }
        rmsnorm_kernel<<<grid_row, blk>>>(x, norm_f_w, x);  // final norm, in-place
    }

    cls_kernel<<<grid_row, blk>>>(g_xa_p, g_xb_p, cls_w, cls_b, out);
}

// round 2
// speedup vs baseline: 1.0988x; 1.0988x over previous
#include <cuda_runtime.h>
#include <math.h>

#define BATCH 32768
#define B2    (2 * BATCH)
#define NL 2

// ---------------- scratch (device globals; no allocation) ----------------
__device__ float g_x [(size_t)B2 * 256];   // both modalities' residual state (rows [0,B)=methyl, [B,2B)=rna)
__device__ float g_xn[(size_t)B2 * 256];   // rmsnorm output
__device__ float g_h [(size_t)B2 * 512];   // post-conv silu activations
__device__ float g_g [(size_t)B2 * 512];   // gate (raw proj)
__device__ float g_y [(size_t)B2 * 512];   // gated ssm output

__device__ __forceinline__ float silu_f(float x) {
    return x / (1.0f + __expf(-x));
}
__device__ __forceinline__ float softplus_f(float x) {
    return (x > 20.0f) ? x : log1pf(__expf(x));
}

// ---------------- 128x128x16 double-buffered fp32 GEMM: C = A[M,K] @ W[N,K]^T ----------------
// MODE 0: out0[m*N+n] = acc + e0[n]                       (bias)
// MODE 1: n<512: silu(acc*conv_w[n*4+3]+conv_b[n]) -> out0 ; n>=512: raw gate -> out1
// MODE 2: out0[m*N+n] = acc + e0[m*N+n]                   (residual add, in-place ok)
#define BM 128
#define BN 128
#define BK 16

template<int MODE>
__global__ __launch_bounds__(256, 2)
void gemm_kernel(const float* __restrict__ A, const float* __restrict__ W,
                 float* __restrict__ out0, float* __restrict__ out1,
                 const float* __restrict__ e0, const float* __restrict__ e1,
                 int N, int K)
{
    __shared__ float As[2][BK][BM];
    __shared__ float Bs[2][BK][BN];

    const int tid = threadIdx.x;
    const int tx  = tid & 15;        // 16 threads over N
    const int ty  = tid >> 4;        // 16 threads over M
    const int bm  = blockIdx.y * BM;
    const int bn  = blockIdx.x * BN;

    float acc[8][8];
    #pragma unroll
    for (int i = 0; i < 8; i++)
        #pragma unroll
        for (int j = 0; j < 8; j++) acc[i][j] = 0.0f;

    const bool vec = ((K & 3) == 0);
    float4 ra[2], rb[2];

    // ---- prologue: load tile k0=0 ----
    #pragma unroll
    for (int i = 0; i < 2; i++) {
        int idx = tid + i * 256;
        int row = idx >> 2;
        int kq  = (idx & 3) * 4;
        float4 va = make_float4(0.f, 0.f, 0.f, 0.f);
        float4 vb = make_float4(0.f, 0.f, 0.f, 0.f);
        if (vec) {
            if (kq + 4 <= K) {
                va = *(const float4*)(A + (size_t)(bm + row) * K + kq);
                vb = *(const float4*)(W + (size_t)(bn + row) * K + kq);
            }
        } else {
            const float* ap = A + (size_t)(bm + row) * K;
            const float* wp = W + (size_t)(bn + row) * K;
            if (kq + 0 < K) { va.x = ap[kq + 0]; vb.x = wp[kq + 0]; }
            if (kq + 1 < K) { va.y = ap[kq + 1]; vb.y = wp[kq + 1]; }
            if (kq + 2 < K) { va.z = ap[kq + 2]; vb.z = wp[kq + 2]; }
            if (kq + 3 < K) { va.w = ap[kq + 3]; vb.w = wp[kq + 3]; }
        }
        ra[i] = va; rb[i] = vb;
    }
    #pragma unroll
    for (int i = 0; i < 2; i++) {
        int idx = tid + i * 256;
        int row = idx >> 2;
        int kq  = (idx & 3) * 4;
        As[0][kq + 0][row] = ra[i].x; As[0][kq + 1][row] = ra[i].y;
        As[0][kq + 2][row] = ra[i].z; As[0][kq + 3][row] = ra[i].w;
        Bs[0][kq + 0][row] = rb[i].x; Bs[0][kq + 1][row] = rb[i].y;
        Bs[0][kq + 2][row] = rb[i].z; Bs[0][kq + 3][row] = rb[i].w;
    }
    __syncthreads();

    int st = 0;
    for (int k0 = 0; k0 < K; k0 += BK) {
        const bool more = (k0 + BK < K);
        if (more) {
            int kbase = k0 + BK;
            #pragma unroll
            for (int i = 0; i < 2; i++) {
                int idx = tid + i * 256;
                int row = idx >> 2;
                int kq  = (idx & 3) * 4;
                int k   = kbase + kq;
                float4 va = make_float4(0.f, 0.f, 0.f, 0.f);
                float4 vb = make_float4(0.f, 0.f, 0.f, 0.f);
                if (vec) {
                    if (k + 4 <= K) {
                        va = *(const float4*)(A + (size_t)(bm + row) * K + k);
                        vb = *(const float4*)(W + (size_t)(bn + row) * K + k);
                    }
                } else {
                    const float* ap = A + (size_t)(bm + row) * K;
                    const float* wp = W + (size_t)(bn + row) * K;
                    if (k + 0 < K) { va.x = ap[k + 0]; vb.x = wp[k + 0]; }
                    if (k + 1 < K) { va.y = ap[k + 1]; vb.y = wp[k + 1]; }
                    if (k + 2 < K) { va.z = ap[k + 2]; vb.z = wp[k + 2]; }
                    if (k + 3 < K) { va.w = ap[k + 3]; vb.w = wp[k + 3]; }
                }
                ra[i] = va; rb[i] = vb;
            }
        }

        #pragma unroll
        for (int kk = 0; kk < BK; kk++) {
            float4 a0 = *(const float4*)&As[st][kk][ty * 4];
            float4 a1 = *(const float4*)&As[st][kk][64 + ty * 4];
            float4 b0 = *(const float4*)&Bs[st][kk][tx * 4];
            float4 b1 = *(const float4*)&Bs[st][kk][64 + tx * 4];
            float av[8] = {a0.x, a0.y, a0.z, a0.w, a1.x, a1.y, a1.z, a1.w};
            float bv[8] = {b0.x, b0.y, b0.z, b0.w, b1.x, b1.y, b1.z, b1.w};
            #pragma unroll
            for (int i = 0; i < 8; i++)
                #pragma unroll
                for (int j = 0; j < 8; j++)
                    acc[i][j] = fmaf(av[i], bv[j], acc[i][j]);
        }

        if (more) {
            int ns = st ^ 1;
            #pragma unroll
            for (int i = 0; i < 2; i++) {
                int idx = tid + i * 256;
                int row = idx >> 2;
                int kq  = (idx & 3) * 4;
                As[ns][kq + 0][row] = ra[i].x; As[ns][kq + 1][row] = ra[i].y;
                As[ns][kq + 2][row] = ra[i].z; As[ns][kq + 3][row] = ra[i].w;
                Bs[ns][kq + 0][row] = rb[i].x; Bs[ns][kq + 1][row] = rb[i].y;
                Bs[ns][kq + 2][row] = rb[i].z; Bs[ns][kq + 3][row] = rb[i].w;
            }
            __syncthreads();
            st = ns;
        }
    }

    // ---- epilogue ----
    #pragma unroll
    for (int i = 0; i < 8; i++) {
        int m = bm + ((i < 4) ? (ty * 4 + i) : (64 + ty * 4 + i - 4));
        #pragma unroll
        for (int h = 0; h < 2; h++) {
            int n = bn + h * 64 + tx * 4;
            float4 v = make_float4(acc[i][h * 4 + 0], acc[i][h * 4 + 1],
                                   acc[i][h * 4 + 2], acc[i][h * 4 + 3]);
            if (MODE == 0) {
                v.x += e0[n + 0]; v.y += e0[n + 1]; v.z += e0[n + 2]; v.w += e0[n + 3];
                *(float4*)(out0 + (size_t)m * N + n) = v;
            } else if (MODE == 1) {
                if (bn < 512) {
                    v.x = silu_f(fmaf(v.x, e0[(n + 0) * 4 + 3], e1[n + 0]));
                    v.y = silu_f(fmaf(v.y, e0[(n + 1) * 4 + 3], e1[n + 1]));
                    v.z = silu_f(fmaf(v.z, e0[(n + 2) * 4 + 3], e1[n + 2]));
                    v.w = silu_f(fmaf(v.w, e0[(n + 3) * 4 + 3], e1[n + 3]));
                    *(float4*)(out0 + (size_t)m * 512 + n) = v;
                } else {
                    *(float4*)(out1 + (size_t)m * 512 + (n - 512)) = v;
                }
            } else {  // MODE 2
                float4 r = *(const float4*)(e0 + (size_t)m * N + n);
                v.x += r.x; v.y += r.y; v.z += r.z; v.w += r.w;
                *(float4*)(out0 + (size_t)m * N + n) = v;
            }
        }
    }
}

// ---------------- fused SSM with smem-staged xp_w ----------------
// warp per row, 16 rows per 512-thread block. xp_w (48x512 = 96KB) staged once per block.
__global__ __launch_bounds__(512)
void ssm_kernel(const float* __restrict__ h, const float* __restrict__ gate,
                const float* __restrict__ xp_w,   // [48,512]
                const float* __restrict__ dt_w,   // [512,16]
                const float* __restrict__ dt_b,   // [512]
                const float* __restrict__ Dv,     // [512]
                float* __restrict__ y)
{
    extern __shared__ float s_xp[];   // 48*512 floats = 96KB
    #pragma unroll 4
    for (int i = threadIdx.x; i < 48 * 512; i += 512)
        s_xp[i] = xp_w[i];
    __syncthreads();

    const int warp = threadIdx.x >> 5;
    const int lane = threadIdx.x & 31;
    const size_t row = (size_t)blockIdx.x * 16 + warp;

    const float* hr = h + row * 512;
    float hreg[16];
    #pragma unroll
    for (int q = 0; q < 16; q++) hreg[q] = hr[lane + 32 * q];

    float dtv[16], bnv[16];
    float bc = 0.0f;
    #pragma unroll
    for (int j = 0; j < 48; j++) {
        const float* w = s_xp + j * 512;
        float p = 0.0f;
        #pragma unroll
        for (int q = 0; q < 16; q++) p = fmaf(hreg[q], w[lane + 32 * q], p);
        #pragma unroll
        for (int o = 16; o > 0; o >>= 1) p += __shfl_xor_sync(0xffffffffu, p, o);
        if (j < 16)       dtv[j] = p;
        else if (j < 32)  bnv[j - 16] = p;
        else              bc = fmaf(bnv[j - 32], p, bc);
    }

    #pragma unroll
    for (int q = 0; q < 16; q++) {
        int i = lane + 32 * q;
        const float4* wr = (const float4*)(dt_w + (size_t)i * 16);
        float t = dt_b[i];
        #pragma unroll
        for (int c = 0; c < 4; c++) {
            float4 w4 = wr[c];
            t = fmaf(dtv[c * 4 + 0], w4.x, t);
            t = fmaf(dtv[c * 4 + 1], w4.y, t);
            t = fmaf(dtv[c * 4 + 2], w4.z, t);
            t = fmaf(dtv[c * 4 + 3], w4.w, t);
        }
        float sp = softplus_f(t);
        float gv = gate[row * 512 + i];
        y[row * 512 + i] = hreg[q] * fmaf(sp, bc, Dv[i]) * silu_f(gv);
    }
}

// ---------------- rmsnorm over 256, warp per row ----------------
__global__ __launch_bounds__(256)
void rmsnorm_kernel(const float* __restrict__ x, const float* __restrict__ w,
                    float* __restrict__ out)
{
    const int warp = threadIdx.x >> 5;
    const int lane = threadIdx.x & 31;
    const size_t row = (size_t)blockIdx.x * 8 + warp;

    float v[8];
    float ss = 0.0f;
    #pragma unroll
    for (int q = 0; q < 8; q++) {
        v[q] = x[row * 256 + lane + 32 * q];
        ss = fmaf(v[q], v[q], ss);
    }
    #pragma unroll
    for (int o = 16; o > 0; o >>= 1) ss += __shfl_xor_sync(0xffffffffu, ss, o);
    float inv = rsqrtf(ss * (1.0f / 256.0f) + 1e-5f);
    #pragma unroll
    for (int q = 0; q < 8; q++)
        out[row * 256 + lane + 32 * q] = v[q] * inv * w[lane + 32 * q];
}

// ---------------- classifier ----------------
__global__ __launch_bounds__(256)
void cls_kernel(const float* __restrict__ x,
                const float* __restrict__ cw, const float* __restrict__ cb,
                float* __restrict__ out)
{
    const int warp = threadIdx.x >> 5;
    const int lane = threadIdx.x & 31;
    const size_t row = (size_t)blockIdx.x * 8 + warp;

    float p[8];
    #pragma unroll
    for (int q = 0; q < 8; q++) {
        size_t ia = row * 256 + lane + 32 * q;
        size_t ib = ((size_t)BATCH + row) * 256 + lane + 32 * q;
        p[q] = 0.5f * (x[ia] + x[ib]);
    }
    #pragma unroll
    for (int j = 0; j < 5; j++) {
        float s = 0.0f;
        #pragma unroll
        for (int q = 0; q < 8; q++) s = fmaf(p[q], cw[j * 256 + lane + 32 * q], s);
        #pragma unroll
        for (int o = 16; o > 0; o >>= 1) s += __shfl_xor_sync(0xffffffffu, s, o);
        if (lane == 0) out[row * 5 + j] = s + cb[j];
    }
}

// ---------------- launch ----------------
extern "C" void kernel_launch(void* const* d_in, const int* in_sizes, int n_in,
                              void* d_out, int out_size)
{
    const float* methyl   = (const float*)d_in[0];   // [B,500]
    const float* rna      = (const float*)d_in[1];   // [B,47]
    const float* methyl_w = (const float*)d_in[2];   // [256,500]
    const float* methyl_b = (const float*)d_in[3];   // [256]
    const float* rna_w    = (const float*)d_in[4];   // [256,47]
    const float* rna_b    = (const float*)d_in[5];   // [256]
    const float* in_w     = (const float*)d_in[6];   // [2,1024,256]
    const float* conv_w   = (const float*)d_in[7];   // [2,512,4]
    const float* conv_b   = (const float*)d_in[8];   // [2,512]
    const float* xp_w     = (const float*)d_in[9];   // [2,48,512]
    const float* dt_w     = (const float*)d_in[10];  // [2,512,16]
    const float* dt_b     = (const float*)d_in[11];  // [2,512]
    // d_in[12] = A_log : unused (scan starts from zero state, L=1)
    const float* Dv       = (const float*)d_in[13];  // [2,512]
    const float* out_w    = (const float*)d_in[14];  // [2,256,512]
    const float* norm_w   = (const float*)d_in[15];  // [2,256]
    const float* norm_f_w = (const float*)d_in[16];  // [256]
    const float* cls_w    = (const float*)d_in[17];  // [5,256]
    const float* cls_b    = (const float*)d_in[18];  // [5]
    float* out = (float*)d_out;

    float* g_x_p;  cudaGetSymbolAddress((void**)&g_x_p,  g_x);
    float* g_xn_p; cudaGetSymbolAddress((void**)&g_xn_p, g_xn);
    float* g_h_p;  cudaGetSymbolAddress((void**)&g_h_p,  g_h);
    float* g_g_p;  cudaGetSymbolAddress((void**)&g_g_p,  g_g);
    float* g_y_p;  cudaGetSymbolAddress((void**)&g_y_p,  g_y);

    static bool attr_done = false;
    if (!attr_done) {
        cudaFuncSetAttribute(ssm_kernel, cudaFuncAttributeMaxDynamicSharedMemorySize,
                             48 * 512 * sizeof(float));
        attr_done = true;
    }

    dim3 blk(256);
    dim3 grid_emb(256 / BN, BATCH / BM);     // N=256, M=BATCH per modality
    dim3 grid_proj(1024 / BN, B2 / BM);      // N=1024, M=2B
    dim3 grid_out(256 / BN, B2 / BM);        // N=256,  M=2B
    dim3 grid_row(B2 / 8);
    dim3 grid_ssm(B2 / 16);
    dim3 grid_cls(BATCH / 8);

    // embeddings -> g_x rows [0,B) and [B,2B)
    gemm_kernel<0><<<grid_emb, blk>>>(methyl, methyl_w, g_x_p, nullptr, methyl_b, nullptr, 256, 500);
    gemm_kernel<0><<<grid_emb, blk>>>(rna,    rna_w,    g_x_p + (size_t)BATCH * 256, nullptr, rna_b, nullptr, 256, 47);

    for (int l = 0; l < NL; l++) {
        rmsnorm_kernel<<<grid_row, blk>>>(g_x_p, norm_w + l * 256, g_xn_p);
        gemm_kernel<1><<<grid_proj, blk>>>(g_xn_p, in_w + (size_t)l * 1024 * 256,
                                           g_h_p, g_g_p,
                                           conv_w + (size_t)l * 512 * 4,
                                           conv_b + (size_t)l * 512, 1024, 256);
        ssm_kernel<<<grid_ssm, 512, 48 * 512 * sizeof(float)>>>(
            g_h_p, g_g_p,
            xp_w + (size_t)l * 48 * 512,
            dt_w + (size_t)l * 512 * 16,
            dt_b + (size_t)l * 512,
            Dv   + (size_t)l * 512, g_y_p);
        gemm_kernel<2><<<grid_out, blk>>>(g_y_p, out_w + (size_t)l * 256 * 512,
                                          g_x_p, nullptr, g_x_p, nullptr, 256, 512);
    }
    rmsnorm_kernel<<<grid_row, blk>>>(g_x_p, norm_f_w, g_x_p);  // final norm, in-place

    cls_kernel<<<grid_cls, blk>>>(g_x_p, cls_w, cls_b, out);
}

// round 6
// speedup vs baseline: 1.5121x; 1.3762x over previous
#include <cuda_runtime.h>
#include <cuda_bf16.h>
#include <math.h>
#include <stdint.h>

#define BATCH 32768
#define B2    (2 * BATCH)
#define NL 2

// ---------------- scratch (device globals; no allocation) ----------------
__device__ float g_x [(size_t)B2 * 256];
__device__ float g_xn[(size_t)B2 * 256];
__device__ float g_h [(size_t)B2 * 512];
__device__ float g_g [(size_t)B2 * 512];
__device__ float g_y [(size_t)B2 * 512];

__device__ __forceinline__ float silu_f(float x) { return x / (1.0f + __expf(-x)); }
__device__ __forceinline__ float softplus_f(float x) { return (x > 20.0f) ? x : log1pf(__expf(x)); }

__device__ __forceinline__ uint32_t smem_u32_of(const void* p) {
    uint32_t a;
    asm("{ .reg .u64 t; cvta.to.shared.u64 t, %1; cvt.u32.u64 %0, t; }" : "=r"(a) : "l"(p));
    return a;
}

// SW128 swizzle on byte offsets (rows are 128B wide)
__device__ __forceinline__ uint32_t swzb(uint32_t b) { return b ^ ((b >> 3) & 0x70); }

#define STS128U(addr, a, b, c, d) \
    asm volatile("st.shared.v4.b32 [%0], {%1, %2, %3, %4};" \
                 :: "r"(addr), "r"(a), "r"(b), "r"(c), "r"(d) : "memory")

#define LDSM4(r0, r1, r2, r3, a) \
    asm volatile("ldmatrix.sync.aligned.m8n8.x4.shared.b16 {%0,%1,%2,%3}, [%4];" \
                 : "=r"(r0), "=r"(r1), "=r"(r2), "=r"(r3) : "r"(a))

__device__ __forceinline__ void mma_bf16(float* c, const uint32_t* a, const uint32_t* b) {
    asm volatile("mma.sync.aligned.m16n8k16.row.col.f32.bf16.bf16.f32 "
                 "{%0,%1,%2,%3}, {%4,%5,%6,%7}, {%8,%9}, {%0,%1,%2,%3};"
                 : "+f"(c[0]), "+f"(c[1]), "+f"(c[2]), "+f"(c[3])
                 : "r"(a[0]), "r"(a[1]), "r"(a[2]), "r"(a[3]), "r"(b[0]), "r"(b[1]));
}

// ---------------- tensor-core GEMM: C[M,N] = A[M,K] @ W[N,K]^T (3x bf16 split) ----------------
// CTA tile 128x128, BK=64. Warps 2(M) x 4(N), warp tile 64x32.
// MODE 0: out0 = acc + e0[n]
// MODE 1: n<512: silu(acc*e0[n*4+3]+e1[n]) -> out0 ; else raw -> out1[m*512+(n-512)]
// MODE 2: out0 = acc + e0[m*N+n]
#define GBK 64
#define TILE_BYTES  (128 * 128)            // 128 rows x 128B (64 bf16)
#define STAGE_BYTES (4 * TILE_BYTES)       // Ahi, Alo, Whi, Wlo
#define GEMM_SMEM   (2 * STAGE_BYTES)      // double buffered = 128KB

template<int MODE>
__global__ __launch_bounds__(256, 1)
void gemm_tc(const float* __restrict__ A, const float* __restrict__ W,
             float* __restrict__ out0, float* __restrict__ out1,
             const float* __restrict__ e0, const float* __restrict__ e1,
             int N, int K)
{
    extern __shared__ char smem[];
    const uint32_t sb = smem_u32_of(smem);

    const int tid  = threadIdx.x;
    const int lane = tid & 31;
    const int wid  = tid >> 5;
    const int bm = blockIdx.y * 128;
    const int bn = blockIdx.x * 128;
    const int wm = (wid >> 2) * 64;     // 0 or 64
    const int wn = (wid & 3) * 32;      // 0..96

    const int S  = (K + GBK - 1) / GBK;
    const bool k4 = ((K & 3) == 0);

    float acc[4][4][4];
    #pragma unroll
    for (int i = 0; i < 4; i++)
        #pragma unroll
        for (int j = 0; j < 4; j++)
            #pragma unroll
            for (int c = 0; c < 4; c++) acc[i][j][c] = 0.0f;

    float va[4][8], vw[4][8];

    // ---- load a 128x64 fp32 chunk-set for stage s into registers ----
    auto load_regs = [&](int s) {
        const int k0 = s * GBK;
        #pragma unroll
        for (int i = 0; i < 4; i++) {
            int idx = tid + i * 256;
            int m  = idx >> 3;          // 0..127
            int c8 = idx & 7;           // 8-wide k chunk
            int k  = k0 + c8 * 8;
            const float* ap = A + (size_t)(bm + m) * K;
            const float* wp = W + (size_t)(bn + m) * K;
            if (k4) {
                #pragma unroll
                for (int h = 0; h < 2; h++) {
                    int kk = k + h * 4;
                    float4 u = make_float4(0.f, 0.f, 0.f, 0.f);
                    float4 v = make_float4(0.f, 0.f, 0.f, 0.f);
                    if (kk + 4 <= K) {
                        u = *(const float4*)(ap + kk);
                        v = *(const float4*)(wp + kk);
                    }
                    va[i][h*4+0] = u.x; va[i][h*4+1] = u.y; va[i][h*4+2] = u.z; va[i][h*4+3] = u.w;
                    vw[i][h*4+0] = v.x; vw[i][h*4+1] = v.y; vw[i][h*4+2] = v.z; vw[i][h*4+3] = v.w;
                }
            } else {
                #pragma unroll
                for (int e = 0; e < 8; e++) {
                    int kk = k + e;
                    va[i][e] = (kk < K) ? ap[kk] : 0.0f;
                    vw[i][e] = (kk < K) ? wp[kk] : 0.0f;
                }
            }
        }
    };

    // ---- split fp32 -> (bf16 hi, bf16 lo), swizzled STS into stage st ----
    auto store_stage = [&](int st) {
        const uint32_t base = sb + st * STAGE_BYTES;
        #pragma unroll
        for (int i = 0; i < 4; i++) {
            int idx = tid + i * 256;
            int m  = idx >> 3;
            int c8 = idx & 7;
            uint32_t off = swzb((uint32_t)(m * 128 + c8 * 16));
            uint32_t hi[4], lo[4];
            #pragma unroll
            for (int p = 0; p < 4; p++) {
                float x0 = va[i][2*p], x1 = va[i][2*p+1];
                __nv_bfloat16 h0 = __float2bfloat16_rn(x0), h1 = __float2bfloat16_rn(x1);
                float r0 = x0 - __bfloat162float(h0), r1 = x1 - __bfloat162float(h1);
                __nv_bfloat16 l0 = __float2bfloat16_rn(r0), l1 = __float2bfloat16_rn(r1);
                hi[p] = ((uint32_t)__bfloat16_as_ushort(h1) << 16) | __bfloat16_as_ushort(h0);
                lo[p] = ((uint32_t)__bfloat16_as_ushort(l1) << 16) | __bfloat16_as_ushort(l0);
            }
            STS128U(base + 0 * TILE_BYTES + off, hi[0], hi[1], hi[2], hi[3]);
            STS128U(base + 1 * TILE_BYTES + off, lo[0], lo[1], lo[2], lo[3]);
            #pragma unroll
            for (int p = 0; p < 4; p++) {
                float x0 = vw[i][2*p], x1 = vw[i][2*p+1];
                __nv_bfloat16 h0 = __float2bfloat16_rn(x0), h1 = __float2bfloat16_rn(x1);
                float r0 = x0 - __bfloat162float(h0), r1 = x1 - __bfloat162float(h1);
                __nv_bfloat16 l0 = __float2bfloat16_rn(r0), l1 = __float2bfloat16_rn(r1);
                hi[p] = ((uint32_t)__bfloat16_as_ushort(h1) << 16) | __bfloat16_as_ushort(h0);
                lo[p] = ((uint32_t)__bfloat16_as_ushort(l1) << 16) | __bfloat16_as_ushort(l0);
            }
            STS128U(base + 2 * TILE_BYTES + off, hi[0], hi[1], hi[2], hi[3]);
            STS128U(base + 3 * TILE_BYTES + off, lo[0], lo[1], lo[2], lo[3]);
        }
    };

    // ---- MMA over one staged BK=64 slab ----
    const int q = lane >> 3;     // ldmatrix matrix index this thread addresses
    const int r = lane & 7;      // row within matrix
    auto mma_stage = [&](int st) {
        const uint32_t base = sb + st * STAGE_BYTES;
        const uint32_t Ah = base, Al = base + TILE_BYTES;
        const uint32_t Wh = base + 2 * TILE_BYTES, Wl = base + 3 * TILE_BYTES;
        #pragma unroll
        for (int kb = 0; kb < 4; kb++) {           // four k16 steps
            uint32_t ah[4][4], al[4][4];
            #pragma unroll
            for (int i = 0; i < 4; i++) {
                uint32_t off = swzb((uint32_t)((wm + 16*i + (q & 1) * 8 + r) * 128
                                               + kb * 32 + (q >> 1) * 16));
                LDSM4(ah[i][0], ah[i][1], ah[i][2], ah[i][3], Ah + off);
                LDSM4(al[i][0], al[i][1], al[i][2], al[i][3], Al + off);
            }
            #pragma unroll
            for (int np = 0; np < 2; np++) {       // n-tile pairs
                uint32_t offb = swzb((uint32_t)((wn + 16*np + (q >> 1) * 8 + r) * 128
                                                + kb * 32 + (q & 1) * 16));
                uint32_t bh[4], bl[4];
                LDSM4(bh[0], bh[1], bh[2], bh[3], Wh + offb);
                LDSM4(bl[0], bl[1], bl[2], bl[3], Wl + offb);
                #pragma unroll
                for (int jj = 0; jj < 2; jj++) {
                    int j = np * 2 + jj;
                    uint32_t Bh[2] = {bh[2*jj], bh[2*jj+1]};
                    uint32_t Bl[2] = {bl[2*jj], bl[2*jj+1]};
                    #pragma unroll
                    for (int i = 0; i < 4; i++) {
                        mma_bf16(acc[i][j], ah[i], Bh);
                        mma_bf16(acc[i][j], ah[i], Bl);
                        mma_bf16(acc[i][j], al[i], Bh);
                    }
                }
            }
        }
    };

    // ---- pipeline ----
    load_regs(0);
    store_stage(0);
    __syncthreads();
    for (int s = 0; s < S; s++) {
        if (s + 1 < S) load_regs(s + 1);   // LDG overlapped with MMA below
        mma_stage(s & 1);
        if (s + 1 < S) store_stage((s + 1) & 1);
        __syncthreads();
    }

    // ---- epilogue ----
    #pragma unroll
    for (int i = 0; i < 4; i++) {
        int r0 = bm + wm + 16 * i + (lane >> 2);
        #pragma unroll
        for (int j = 0; j < 4; j++) {
            int c = bn + wn + 8 * j + (lane & 3) * 2;
            #pragma unroll
            for (int hrow = 0; hrow < 2; hrow++) {
                int m = r0 + hrow * 8;
                float v0 = acc[i][j][hrow * 2 + 0];
                float v1 = acc[i][j][hrow * 2 + 1];
                if (MODE == 0) {
                    float2 o = make_float2(v0 + e0[c], v1 + e0[c + 1]);
                    *(float2*)(out0 + (size_t)m * N + c) = o;
                } else if (MODE == 1) {
                    if (c < 512) {
                        float2 o;
                        o.x = silu_f(fmaf(v0, e0[c * 4 + 3], e1[c]));
                        o.y = silu_f(fmaf(v1, e0[(c + 1) * 4 + 3], e1[c + 1]));
                        *(float2*)(out0 + (size_t)m * 512 + c) = o;
                    } else {
                        *(float2*)(out1 + (size_t)m * 512 + (c - 512)) = make_float2(v0, v1);
                    }
                } else {
                    float2 rr = *(const float2*)(e0 + (size_t)m * N + c);
                    *(float2*)(out0 + (size_t)m * N + c) = make_float2(v0 + rr.x, v1 + rr.y);
                }
            }
        }
    }
}

// ---------------- fused SSM with smem-staged xp_w ----------------
__global__ __launch_bounds__(512)
void ssm_kernel(const float* __restrict__ h, const float* __restrict__ gate,
                const float* __restrict__ xp_w, const float* __restrict__ dt_w,
                const float* __restrict__ dt_b, const float* __restrict__ Dv,
                float* __restrict__ y)
{
    extern __shared__ float s_xp[];
    #pragma unroll 4
    for (int i = threadIdx.x; i < 48 * 512; i += 512) s_xp[i] = xp_w[i];
    __syncthreads();

    const int warp = threadIdx.x >> 5;
    const int lane = threadIdx.x & 31;
    const size_t row = (size_t)blockIdx.x * 16 + warp;

    const float* hr = h + row * 512;
    float hreg[16];
    #pragma unroll
    for (int qq = 0; qq < 16; qq++) hreg[qq] = hr[lane + 32 * qq];

    float dtv[16], bnv[16];
    float bc = 0.0f;
    #pragma unroll
    for (int j = 0; j < 48; j++) {
        const float* w = s_xp + j * 512;
        float p = 0.0f;
        #pragma unroll
        for (int qq = 0; qq < 16; qq++) p = fmaf(hreg[qq], w[lane + 32 * qq], p);
        #pragma unroll
        for (int o = 16; o > 0; o >>= 1) p += __shfl_xor_sync(0xffffffffu, p, o);
        if (j < 16)       dtv[j] = p;
        else if (j < 32)  bnv[j - 16] = p;
        else              bc = fmaf(bnv[j - 32], p, bc);
    }

    #pragma unroll
    for (int qq = 0; qq < 16; qq++) {
        int i = lane + 32 * qq;
        const float4* wr = (const float4*)(dt_w + (size_t)i * 16);
        float t = dt_b[i];
        #pragma unroll
        for (int c = 0; c < 4; c++) {
            float4 w4 = wr[c];
            t = fmaf(dtv[c * 4 + 0], w4.x, t);
            t = fmaf(dtv[c * 4 + 1], w4.y, t);
            t = fmaf(dtv[c * 4 + 2], w4.z, t);
            t = fmaf(dtv[c * 4 + 3], w4.w, t);
        }
        float sp = softplus_f(t);
        float gv = gate[row * 512 + i];
        y[row * 512 + i] = hreg[qq] * fmaf(sp, bc, Dv[i]) * silu_f(gv);
    }
}

// ---------------- rmsnorm ----------------
__global__ __launch_bounds__(256)
void rmsnorm_kernel(const float* __restrict__ x, const float* __restrict__ w,
                    float* __restrict__ out)
{
    const int warp = threadIdx.x >> 5;
    const int lane = threadIdx.x & 31;
    const size_t row = (size_t)blockIdx.x * 8 + warp;

    float v[8];
    float ss = 0.0f;
    #pragma unroll
    for (int qq = 0; qq < 8; qq++) {
        v[qq] = x[row * 256 + lane + 32 * qq];
        ss = fmaf(v[qq], v[qq], ss);
    }
    #pragma unroll
    for (int o = 16; o > 0; o >>= 1) ss += __shfl_xor_sync(0xffffffffu, ss, o);
    float inv = rsqrtf(ss * (1.0f / 256.0f) + 1e-5f);
    #pragma unroll
    for (int qq = 0; qq < 8; qq++)
        out[row * 256 + lane + 32 * qq] = v[qq] * inv * w[lane + 32 * qq];
}

// ---------------- classifier ----------------
__global__ __launch_bounds__(256)
void cls_kernel(const float* __restrict__ x,
                const float* __restrict__ cw, const float* __restrict__ cb,
                float* __restrict__ out)
{
    const int warp = threadIdx.x >> 5;
    const int lane = threadIdx.x & 31;
    const size_t row = (size_t)blockIdx.x * 8 + warp;

    float p[8];
    #pragma unroll
    for (int qq = 0; qq < 8; qq++) {
        size_t ia = row * 256 + lane + 32 * qq;
        size_t ib = ((size_t)BATCH + row) * 256 + lane + 32 * qq;
        p[qq] = 0.5f * (x[ia] + x[ib]);
    }
    #pragma unroll
    for (int j = 0; j < 5; j++) {
        float s = 0.0f;
        #pragma unroll
        for (int qq = 0; qq < 8; qq++) s = fmaf(p[qq], cw[j * 256 + lane + 32 * qq], s);
        #pragma unroll
        for (int o = 16; o > 0; o >>= 1) s += __shfl_xor_sync(0xffffffffu, s, o);
        if (lane == 0) out[row * 5 + j] = s + cb[j];
    }
}

// ---------------- launch ----------------
extern "C" void kernel_launch(void* const* d_in, const int* in_sizes, int n_in,
                              void* d_out, int out_size)
{
    const float* methyl   = (const float*)d_in[0];
    const float* rna      = (const float*)d_in[1];
    const float* methyl_w = (const float*)d_in[2];
    const float* methyl_b = (const float*)d_in[3];
    const float* rna_w    = (const float*)d_in[4];
    const float* rna_b    = (const float*)d_in[5];
    const float* in_w     = (const float*)d_in[6];
    const float* conv_w   = (const float*)d_in[7];
    const float* conv_b   = (const float*)d_in[8];
    const float* xp_w     = (const float*)d_in[9];
    const float* dt_w     = (const float*)d_in[10];
    const float* dt_b     = (const float*)d_in[11];
    const float* Dv       = (const float*)d_in[13];
    const float* out_w    = (const float*)d_in[14];
    const float* norm_w   = (const float*)d_in[15];
    const float* norm_f_w = (const float*)d_in[16];
    const float* cls_w    = (const float*)d_in[17];
    const float* cls_b    = (const float*)d_in[18];
    float* out = (float*)d_out;

    float* g_x_p;  cudaGetSymbolAddress((void**)&g_x_p,  g_x);
    float* g_xn_p; cudaGetSymbolAddress((void**)&g_xn_p, g_xn);
    float* g_h_p;  cudaGetSymbolAddress((void**)&g_h_p,  g_h);
    float* g_g_p;  cudaGetSymbolAddress((void**)&g_g_p,  g_g);
    float* g_y_p;  cudaGetSymbolAddress((void**)&g_y_p,  g_y);

    // idempotent, called every launch (no static guards per harness rules)
    cudaFuncSetAttribute(ssm_kernel, cudaFuncAttributeMaxDynamicSharedMemorySize, 48 * 512 * sizeof(float));
    cudaFuncSetAttribute(gemm_tc<0>, cudaFuncAttributeMaxDynamicSharedMemorySize, GEMM_SMEM);
    cudaFuncSetAttribute(gemm_tc<1>, cudaFuncAttributeMaxDynamicSharedMemorySize, GEMM_SMEM);
    cudaFuncSetAttribute(gemm_tc<2>, cudaFuncAttributeMaxDynamicSharedMemorySize, GEMM_SMEM);

    dim3 blk(256);
    dim3 grid_emb(256 / 128, BATCH / 128);
    dim3 grid_proj(1024 / 128, B2 / 128);
    dim3 grid_out(256 / 128, B2 / 128);
    dim3 grid_row(B2 / 8);
    dim3 grid_ssm(B2 / 16);
    dim3 grid_cls(BATCH / 8);

    gemm_tc<0><<<grid_emb, blk, GEMM_SMEM>>>(methyl, methyl_w, g_x_p, nullptr, methyl_b, nullptr, 256, 500);
    gemm_tc<0><<<grid_emb, blk, GEMM_SMEM>>>(rna, rna_w, g_x_p + (size_t)BATCH * 256, nullptr, rna_b, nullptr, 256, 47);

    for (int l = 0; l < NL; l++) {
        rmsnorm_kernel<<<grid_row, blk>>>(g_x_p, norm_w + l * 256, g_xn_p);
        gemm_tc<1><<<grid_proj, blk, GEMM_SMEM>>>(g_xn_p, in_w + (size_t)l * 1024 * 256,
                                                  g_h_p, g_g_p,
                                                  conv_w + (size_t)l * 512 * 4,
                                                  conv_b + (size_t)l * 512, 1024, 256);
        ssm_kernel<<<grid_ssm, 512, 48 * 512 * sizeof(float)>>>(
            g_h_p, g_g_p,
            xp_w + (size_t)l * 48 * 512,
            dt_w + (size_t)l * 512 * 16,
            dt_b + (size_t)l * 512,
            Dv   + (size_t)l * 512, g_y_p);
        gemm_tc<2><<<grid_out, blk, GEMM_SMEM>>>(g_y_p, out_w + (size_t)l * 256 * 512,
                                                 g_x_p, nullptr, g_x_p, nullptr, 256, 512);
    }
    rmsnorm_kernel<<<grid_row, blk>>>(g_x_p, norm_f_w, g_x_p);

    cls_kernel<<<grid_cls, blk>>>(g_x_p, cls_w, cls_b, out);
}